// round 17
// baseline (speedup 1.0000x reference)
#include <cuda_runtime.h>
#include <cuda_bf16.h>

#define FULL_MASK 0xFFFFFFFFu

// One warp per ray; each lane owns SIX consecutive samples (192 = 32*6).
// All loads front-batched (15 LDG.64 -> high MLP). Single prefix-product scan
// over the per-lane product of 6 survival factors (5 shfl rounds total).
// rgb is fully lane-local with aligned channel triplets -> zero gather work.
__global__ void __launch_bounds__(256) nerf_render_kernel(
    const float* __restrict__ rgb,     // [N, S, 3]
    const float* __restrict__ sigma,   // [N, S]
    const float* __restrict__ z_vals,  // [N, S]
    const float* __restrict__ rays_d,  // [N, 3]
    float* __restrict__ out,           // flattened 7-tuple
    int N)
{
    const int S = 192;
    const int warp_id = (int)((blockIdx.x * blockDim.x + threadIdx.x) >> 5);
    const int lane    = threadIdx.x & 31;
    if (warp_id >= N) return;
    const int ray = warp_id;

    const size_t NS = (size_t)N * (size_t)S;
    float* out_rgb   = out;
    float* out_depth = out + (size_t)3 * N;
    float* out_acc   = out + (size_t)4 * N;
    float* out_w     = out + (size_t)5 * N;
    float* out_disp  = out + (size_t)5 * N + NS;
    float* out_trans = out + (size_t)6 * N + NS;
    float* out_alpha = out + (size_t)6 * N + 2 * NS;

    const float2* zr2 = (const float2*)(z_vals + (size_t)ray * S);
    const float2* sr2 = (const float2*)(sigma  + (size_t)ray * S);
    const float2* cr2 = (const float2*)(rgb    + (size_t)ray * S * 3);
    float2* wr2 = (float2*)(out_w     + (size_t)ray * S);
    float2* tr2 = (float2*)(out_trans + (size_t)ray * S);
    float2* ar2 = (float2*)(out_alpha + (size_t)ray * S);

    // ---------------- Phase A: batch ALL global loads (15 LDG.64) -----------
    // lane owns samples [6l, 6l+6): z/sigma = 3 LDG.64 each, rgb = 9 LDG.64
    float zf[6], sf[6], vf[18];
    #pragma unroll
    for (int k = 0; k < 3; k++) {
        float2 a = __ldcs(zr2 + 3 * lane + k);
        zf[2 * k] = a.x; zf[2 * k + 1] = a.y;
    }
    #pragma unroll
    for (int k = 0; k < 3; k++) {
        float2 a = __ldcs(sr2 + 3 * lane + k);
        sf[2 * k] = a.x; sf[2 * k + 1] = a.y;
    }
    #pragma unroll
    for (int k = 0; k < 9; k++) {
        float2 a = __ldcs(cr2 + 9 * lane + k);
        vf[2 * k] = a.x; vf[2 * k + 1] = a.y;
    }
    const float dx = rays_d[ray * 3 + 0];
    const float dy = rays_d[ray * 3 + 1];
    const float dz = rays_d[ray * 3 + 2];
    const float norm = sqrtf(dx * dx + dy * dy + dz * dz);

    // ---------------- Phase B: survival factors ----------------------------
    // dists 0..4 are register-local; dist 5 needs next lane's zf[0]
    const float znext = __shfl_down_sync(FULL_MASK, zf[0], 1);
    float tf[6];
    #pragma unroll
    for (int j = 0; j < 5; j++) {
        const float x = fmaxf(sf[j], 0.0f) * ((zf[j + 1] - zf[j]) * norm);
        tf[j] = __expf(-x);
    }
    {
        const float dist5 = (lane == 31) ? 1e10f : (znext - zf[5]);
        const float x = fmaxf(sf[5], 0.0f) * (dist5 * norm);
        tf[5] = __expf(-x);
    }

    // ---------------- Phase C: single scan over 6-fold products -------------
    float p = ((tf[0] * tf[1]) * (tf[2] * tf[3])) * (tf[4] * tf[5]);
    #pragma unroll
    for (int off = 1; off < 32; off <<= 1) {
        float q = __shfl_up_sync(FULL_MASK, p, off);
        if (lane >= off) p *= q;
    }
    float excl = __shfl_up_sync(FULL_MASK, p, 1);
    if (lane == 0) excl = 1.0f;

    // ---------------- Phase D: local trans/weights -------------------------
    float trans[6], w[6];
    trans[0] = excl;
    #pragma unroll
    for (int j = 0; j < 5; j++) trans[j + 1] = trans[j] * tf[j];
    #pragma unroll
    for (int j = 0; j < 6; j++) w[j] = (1.0f - tf[j]) * trans[j];

    // ---------------- Phase E: stores + lane-local accumulation -------------
    #pragma unroll
    for (int k = 0; k < 3; k++) {
        __stcs(wr2 + 3 * lane + k, make_float2(w[2 * k],     w[2 * k + 1]));
        __stcs(tr2 + 3 * lane + k, make_float2(trans[2 * k], trans[2 * k + 1]));
        __stcs(ar2 + 3 * lane + k, make_float2(1.0f - tf[2 * k], 1.0f - tf[2 * k + 1]));
    }

    float accR = 0.f, accG = 0.f, accB = 0.f, accD = 0.f, accA = 0.f;
    #pragma unroll
    for (int j = 0; j < 6; j++) {
        accR += w[j] * vf[3 * j + 0];
        accG += w[j] * vf[3 * j + 1];
        accB += w[j] * vf[3 * j + 2];
        accD += w[j] * zf[j];
        accA += w[j];
    }

    // warp reduce the 5 scalars
    #pragma unroll
    for (int off = 16; off > 0; off >>= 1) {
        accR += __shfl_down_sync(FULL_MASK, accR, off);
        accG += __shfl_down_sync(FULL_MASK, accG, off);
        accB += __shfl_down_sync(FULL_MASK, accB, off);
        accD += __shfl_down_sync(FULL_MASK, accD, off);
        accA += __shfl_down_sync(FULL_MASK, accA, off);
    }

    if (lane == 0) {
        out_rgb[ray * 3 + 0] = accR;
        out_rgb[ray * 3 + 1] = accG;
        out_rgb[ray * 3 + 2] = accB;
        out_depth[ray] = accD;
        out_acc[ray]   = accA;
        out_disp[ray]  = 1.0f / fmaxf(1e-10f, accD / accA);
    }
}

extern "C" void kernel_launch(void* const* d_in, const int* in_sizes, int n_in,
                              void* d_out, int out_size) {
    const float* rgb    = (const float*)d_in[0];
    const float* sigma  = (const float*)d_in[1];
    const float* z_vals = (const float*)d_in[2];
    const float* rays_d = (const float*)d_in[3];
    float* out = (float*)d_out;

    const int N = in_sizes[3] / 3;          // 65536

    const int threads = 256;                // 8 warps = 8 rays / block
    const int blocks = (N * 32) / threads;  // 8192
    nerf_render_kernel<<<blocks, threads>>>(rgb, sigma, z_vals, rays_d, out, N);
}